// round 1
// baseline (speedup 1.0000x reference)
#include <cuda_runtime.h>
#include <math.h>

// Problem constants
constexpr int BB   = 2;
constexpr int LL   = 1024;
constexpr int DD   = 768;
constexpr int NLAY = 8;
constexpr int DIN  = 1536;       // 2*D
constexpr int NSS  = 16;
constexpr int DRR  = 48;         // D/16
constexpr int KCC  = 4;
constexpr int TT   = BB * LL;    // 2048 tokens
constexpr int NR   = DRR + 2 * NSS;  // 80

// Scratch offsets (floats)
constexpr size_t O_X   = 0;
constexpr size_t O_RES = O_X   + (size_t)TT * DD;
constexpr size_t O_XN  = O_RES + (size_t)TT * DD;
constexpr size_t O_XZ  = O_XN  + (size_t)TT * DD;
constexpr size_t O_XC  = O_XZ  + (size_t)TT * 2 * DIN;
constexpr size_t O_DBC = O_XC  + (size_t)TT * DIN;
constexpr size_t O_DT  = O_DBC + (size_t)TT * NR;
constexpr size_t O_Y   = O_DT  + (size_t)TT * DIN;
constexpr size_t O_END = O_Y   + (size_t)TT * DIN;

__device__ float g_buf[O_END];

// ---------------------------------------------------------------------------
// init: x -> scratch, res = 0
// ---------------------------------------------------------------------------
__global__ void init_kernel(const float* __restrict__ xin,
                            float* __restrict__ x, float* __restrict__ res) {
    int i = blockIdx.x * blockDim.x + threadIdx.x;
    if (i < TT * DD) { x[i] = xin[i]; res[i] = 0.f; }
}

// ---------------------------------------------------------------------------
// Per-layer: res += x ; xn = LayerNorm(x)*w + b   (one block per token, D=768)
// ---------------------------------------------------------------------------
__global__ void __launch_bounds__(256)
layer_ln_kernel(const float* __restrict__ x, float* __restrict__ res,
                float* __restrict__ xn,
                const float* __restrict__ w, const float* __restrict__ b) {
    int row = blockIdx.x;
    const float* xr = x + (size_t)row * DD;
    float* rr = res + (size_t)row * DD;
    float* onr = xn + (size_t)row * DD;
    int tid = threadIdx.x;
    __shared__ float red[256];

    float v0 = xr[tid], v1 = xr[tid + 256], v2 = xr[tid + 512];
    red[tid] = v0 + v1 + v2;
    __syncthreads();
    for (int st = 128; st > 0; st >>= 1) {
        if (tid < st) red[tid] += red[tid + st];
        __syncthreads();
    }
    float mu = red[0] * (1.f / DD);
    __syncthreads();
    float d0 = v0 - mu, d1 = v1 - mu, d2 = v2 - mu;
    red[tid] = d0 * d0 + d1 * d1 + d2 * d2;
    __syncthreads();
    for (int st = 128; st > 0; st >>= 1) {
        if (tid < st) red[tid] += red[tid + st];
        __syncthreads();
    }
    float inv = rsqrtf(red[0] * (1.f / DD) + 1e-5f);
    onr[tid]       = d0 * inv * w[tid]       + b[tid];
    onr[tid + 256] = d1 * inv * w[tid + 256] + b[tid + 256];
    onr[tid + 512] = d2 * inv * w[tid + 512] + b[tid + 512];
    rr[tid]       += v0;
    rr[tid + 256] += v1;
    rr[tid + 512] += v2;
}

// ---------------------------------------------------------------------------
// Final: out = LayerNorm(x + res)*fw + fb
// ---------------------------------------------------------------------------
__global__ void __launch_bounds__(256)
final_ln_kernel(const float* __restrict__ x, const float* __restrict__ res,
                const float* __restrict__ w, const float* __restrict__ b,
                float* __restrict__ out) {
    int row = blockIdx.x;
    const float* xr = x + (size_t)row * DD;
    const float* rr = res + (size_t)row * DD;
    float* o = out + (size_t)row * DD;
    int tid = threadIdx.x;
    __shared__ float red[256];

    float v0 = xr[tid] + rr[tid];
    float v1 = xr[tid + 256] + rr[tid + 256];
    float v2 = xr[tid + 512] + rr[tid + 512];
    red[tid] = v0 + v1 + v2;
    __syncthreads();
    for (int st = 128; st > 0; st >>= 1) {
        if (tid < st) red[tid] += red[tid + st];
        __syncthreads();
    }
    float mu = red[0] * (1.f / DD);
    __syncthreads();
    float d0 = v0 - mu, d1 = v1 - mu, d2 = v2 - mu;
    red[tid] = d0 * d0 + d1 * d1 + d2 * d2;
    __syncthreads();
    for (int st = 128; st > 0; st >>= 1) {
        if (tid < st) red[tid] += red[tid + st];
        __syncthreads();
    }
    float inv = rsqrtf(red[0] * (1.f / DD) + 1e-5f);
    o[tid]       = d0 * inv * w[tid]       + b[tid];
    o[tid + 256] = d1 * inv * w[tid + 256] + b[tid + 256];
    o[tid + 512] = d2 * inv * w[tid + 512] + b[tid + 512];
}

// ---------------------------------------------------------------------------
// Generic tiled fp32 GEMM: C[m,n] = sum_k A[m,k] * W[n,k]  (+ epilogue)
// BM=128, BN=64, BK=16, 256 threads, 8x4 microtile.
// EPI: 0 = plain store, 1 = bias + softplus.
// Requirements: M % 128 == 0, K % 16 == 0, N guarded.
// ---------------------------------------------------------------------------
template <int EPI>
__global__ void __launch_bounds__(256)
gemm_kernel(const float* __restrict__ A, int lda,
            const float* __restrict__ W,
            const float* __restrict__ bias,
            float* __restrict__ C, int ldc,
            int N, int K) {
    __shared__ float As[16][132];
    __shared__ float Ws[16][68];
    const int tid = threadIdx.x;
    const int tx = tid & 15, ty = tid >> 4;
    const int m0 = blockIdx.y * 128, n0 = blockIdx.x * 64;

    const int ar = tid >> 1;          // 0..127
    const int ak = (tid & 1) * 8;     // 0 or 8
    const int wr = tid >> 2;          // 0..63
    const int wk = (tid & 3) * 4;     // 0,4,8,12

    float acc[8][4];
#pragma unroll
    for (int i = 0; i < 8; i++)
#pragma unroll
        for (int j = 0; j < 4; j++) acc[i][j] = 0.f;

    for (int k0 = 0; k0 < K; k0 += 16) {
        const float* ap = A + (size_t)(m0 + ar) * lda + k0 + ak;
        float4 a0 = *(const float4*)(ap);
        float4 a1 = *(const float4*)(ap + 4);
        As[ak + 0][ar] = a0.x; As[ak + 1][ar] = a0.y;
        As[ak + 2][ar] = a0.z; As[ak + 3][ar] = a0.w;
        As[ak + 4][ar] = a1.x; As[ak + 5][ar] = a1.y;
        As[ak + 6][ar] = a1.z; As[ak + 7][ar] = a1.w;

        float4 wv = make_float4(0.f, 0.f, 0.f, 0.f);
        if (n0 + wr < N)
            wv = *(const float4*)(W + (size_t)(n0 + wr) * K + k0 + wk);
        Ws[wk + 0][wr] = wv.x; Ws[wk + 1][wr] = wv.y;
        Ws[wk + 2][wr] = wv.z; Ws[wk + 3][wr] = wv.w;
        __syncthreads();

#pragma unroll
        for (int kk = 0; kk < 16; kk++) {
            float4 av0 = *(const float4*)(&As[kk][ty * 8]);
            float4 av1 = *(const float4*)(&As[kk][ty * 8 + 4]);
            float4 wv0 = *(const float4*)(&Ws[kk][tx * 4]);
            float a[8] = {av0.x, av0.y, av0.z, av0.w, av1.x, av1.y, av1.z, av1.w};
            float w[4] = {wv0.x, wv0.y, wv0.z, wv0.w};
#pragma unroll
            for (int i = 0; i < 8; i++)
#pragma unroll
                for (int j = 0; j < 4; j++)
                    acc[i][j] += a[i] * w[j];
        }
        __syncthreads();
    }

#pragma unroll
    for (int i = 0; i < 8; i++) {
        int m = m0 + ty * 8 + i;
#pragma unroll
        for (int j = 0; j < 4; j++) {
            int n = n0 + tx * 4 + j;
            if (n < N) {
                float v = acc[i][j];
                if (EPI == 1) {
                    v += bias[n];
                    v = (v > 20.f) ? v : log1pf(__expf(v));
                }
                C[(size_t)m * ldc + n] = v;
            }
        }
    }
}

// ---------------------------------------------------------------------------
// Causal depthwise conv (KC=4, left pad 3) + bias + SiLU.
// xi = xz[:, :DIN]; xc[b,t,c] = silu(sum_k xi[b, t-3+k, c] * w[c,k] + cb[c])
// ---------------------------------------------------------------------------
__global__ void __launch_bounds__(256)
conv_kernel(const float* __restrict__ xz, float* __restrict__ xc,
            const float* __restrict__ cw, const float* __restrict__ cb) {
    int idx = blockIdx.x * blockDim.x + threadIdx.x;
    if (idx >= TT * DIN) return;
    int c = idx % DIN;
    int tb = idx / DIN;
    int t = tb % LL;
    int b = tb / LL;
    float acc = cb[c];
#pragma unroll
    for (int k = 0; k < KCC; k++) {
        int tt = t - (KCC - 1) + k;
        if (tt >= 0)
            acc += cw[c * KCC + k] * xz[((size_t)(b * LL + tt)) * (2 * DIN) + c];
    }
    float sg = 1.f / (1.f + __expf(-acc));
    xc[idx] = acc * sg;
}

// ---------------------------------------------------------------------------
// Selective scan. Warp = 2 channels x 16 states; thread owns h[b,d,n] scalar.
// y reduced over n by shfl.xor within 16 lanes. Gating fused in epilogue:
//   y_out = (sum_n h*C + xc*Dp) * silu(z)
// Grid: B * (DIN/16) = 192 blocks, 256 threads (16 channels per block).
// ---------------------------------------------------------------------------
__global__ void __launch_bounds__(256)
scan_kernel(const float* __restrict__ dt, const float* __restrict__ xc,
            const float* __restrict__ dbc, const float* __restrict__ xz,
            float* __restrict__ y,
            const float* __restrict__ Alog, const float* __restrict__ Dp) {
    int warp = threadIdx.x >> 5;
    int lane = threadIdx.x & 31;
    int n = lane & 15;
    int dl = lane >> 4;
    constexpr int BLOCKS_PER_B = DIN / 16;   // 96
    int b = blockIdx.x / BLOCKS_PER_B;
    int d = (blockIdx.x % BLOCKS_PER_B) * 16 + warp * 2 + dl;

    float Av = -__expf(Alog[d * NSS + n]);
    float Dv = Dp[d];
    float h = 0.f;
    size_t rowbase = (size_t)b * LL;

    for (int t = 0; t < LL; t++) {
        size_t row = rowbase + t;
        float dtv = dt[row * DIN + d];
        float xv  = xc[row * DIN + d];
        float Bv  = dbc[row * NR + DRR + n];
        float Cv  = dbc[row * NR + DRR + NSS + n];
        float dA  = __expf(dtv * Av);
        h = dA * h + (dtv * xv) * Bv;
        float yp = h * Cv;
        yp += __shfl_xor_sync(0xffffffffu, yp, 8);
        yp += __shfl_xor_sync(0xffffffffu, yp, 4);
        yp += __shfl_xor_sync(0xffffffffu, yp, 2);
        yp += __shfl_xor_sync(0xffffffffu, yp, 1);
        if (n == 0) {
            float zv = xz[row * (2 * DIN) + DIN + d];
            float sg = zv / (1.f + __expf(-zv));
            y[row * DIN + d] = (yp + xv * Dv) * sg;
        }
    }
}

// ---------------------------------------------------------------------------
// Orchestration
// ---------------------------------------------------------------------------
extern "C" void kernel_launch(void* const* d_in, const int* in_sizes, int n_in,
                              void* d_out, int out_size) {
    const float* x        = (const float*)d_in[0];
    const float* ln_w     = (const float*)d_in[1];
    const float* ln_b     = (const float*)d_in[2];
    const float* in_proj  = (const float*)d_in[3];
    const float* conv_w   = (const float*)d_in[4];
    const float* conv_b   = (const float*)d_in[5];
    const float* x_proj   = (const float*)d_in[6];
    const float* dt_w     = (const float*)d_in[7];
    const float* dt_b     = (const float*)d_in[8];
    const float* A_log    = (const float*)d_in[9];
    const float* D_skip   = (const float*)d_in[10];
    const float* out_proj = (const float*)d_in[11];
    const float* fn_w     = (const float*)d_in[12];
    const float* fn_b     = (const float*)d_in[13];
    float* out = (float*)d_out;

    float* base = nullptr;
    cudaGetSymbolAddress((void**)&base, g_buf);
    float* bx   = base + O_X;
    float* bres = base + O_RES;
    float* bxn  = base + O_XN;
    float* bxz  = base + O_XZ;
    float* bxc  = base + O_XC;
    float* bdbc = base + O_DBC;
    float* bdt  = base + O_DT;
    float* by   = base + O_Y;

    init_kernel<<<(TT * DD) / 256, 256>>>(x, bx, bres);

    for (int l = 0; l < NLAY; l++) {
        layer_ln_kernel<<<TT, 256>>>(bx, bres, bxn,
                                     ln_w + (size_t)l * DD, ln_b + (size_t)l * DD);
        // xz = xn @ Wi^T   (2048 x 3072, K=768)
        gemm_kernel<0><<<dim3((2 * DIN) / 64, TT / 128), 256>>>(
            bxn, DD, in_proj + (size_t)l * 2 * DIN * DD, nullptr,
            bxz, 2 * DIN, 2 * DIN, DD);
        // xc = silu(conv(xi) + cb)
        conv_kernel<<<(TT * DIN) / 256, 256>>>(
            bxz, bxc, conv_w + (size_t)l * DIN * KCC, conv_b + (size_t)l * DIN);
        // dbc = xc @ Wx^T  (2048 x 80, K=1536)
        gemm_kernel<0><<<dim3((NR + 63) / 64, TT / 128), 256>>>(
            bxc, DIN, x_proj + (size_t)l * NR * DIN, nullptr,
            bdbc, NR, NR, DIN);
        // dt = softplus(dbc[:, :48] @ Wdt^T + bdt)  (2048 x 1536, K=48)
        gemm_kernel<1><<<dim3(DIN / 64, TT / 128), 256>>>(
            bdbc, NR, dt_w + (size_t)l * DIN * DRR, dt_b + (size_t)l * DIN,
            bdt, DIN, DIN, DRR);
        // selective scan + gating
        scan_kernel<<<BB * (DIN / 16), 256>>>(
            bdt, bxc, bdbc, bxz, by,
            A_log + (size_t)l * DIN * NSS, D_skip + (size_t)l * DIN);
        // x_next = y @ Wo^T  (2048 x 768, K=1536)
        gemm_kernel<0><<<dim3(DD / 64, TT / 128), 256>>>(
            by, DIN, out_proj + (size_t)l * DD * DIN, nullptr,
            bx, DD, DD, DIN);
    }

    final_ln_kernel<<<TT, 256>>>(bx, bres, fn_w, fn_b, out);
}

// round 2
// speedup vs baseline: 1.2718x; 1.2718x over previous
#include <cuda_runtime.h>
#include <cuda_bf16.h>
#include <math.h>

// Problem constants
constexpr int BB   = 2;
constexpr int LL   = 1024;
constexpr int DD   = 768;
constexpr int NLAY = 8;
constexpr int DIN  = 1536;       // 2*D
constexpr int NSS  = 16;
constexpr int DRR  = 48;         // D/16
constexpr int KCC  = 4;
constexpr int TT   = BB * LL;    // 2048 tokens
constexpr int NR   = DRR + 2 * NSS;  // 80

// Scratch offsets (floats)
constexpr size_t O_X   = 0;
constexpr size_t O_RES = O_X   + (size_t)TT * DD;
constexpr size_t O_XN  = O_RES + (size_t)TT * DD;
constexpr size_t O_XZ  = O_XN  + (size_t)TT * DD;
constexpr size_t O_XC  = O_XZ  + (size_t)TT * 2 * DIN;
constexpr size_t O_DBC = O_XC  + (size_t)TT * DIN;
constexpr size_t O_DT  = O_DBC + (size_t)TT * NR;
constexpr size_t O_Y   = O_DT  + (size_t)TT * DIN;
constexpr size_t O_END = O_Y   + (size_t)TT * DIN;

__device__ float g_buf[O_END];

// ---------------------------------------------------------------------------
// init: x -> scratch, res = 0
// ---------------------------------------------------------------------------
__global__ void init_kernel(const float* __restrict__ xin,
                            float* __restrict__ x, float* __restrict__ res) {
    int i = blockIdx.x * blockDim.x + threadIdx.x;
    if (i < TT * DD) { x[i] = xin[i]; res[i] = 0.f; }
}

// ---------------------------------------------------------------------------
// Per-layer: res += x ; xn = LayerNorm(x)*w + b   (one block per token, D=768)
// ---------------------------------------------------------------------------
__global__ void __launch_bounds__(256)
layer_ln_kernel(const float* __restrict__ x, float* __restrict__ res,
                float* __restrict__ xn,
                const float* __restrict__ w, const float* __restrict__ b) {
    int row = blockIdx.x;
    const float* xr = x + (size_t)row * DD;
    float* rr = res + (size_t)row * DD;
    float* onr = xn + (size_t)row * DD;
    int tid = threadIdx.x;
    __shared__ float red[256];

    float v0 = xr[tid], v1 = xr[tid + 256], v2 = xr[tid + 512];
    red[tid] = v0 + v1 + v2;
    __syncthreads();
    for (int st = 128; st > 0; st >>= 1) {
        if (tid < st) red[tid] += red[tid + st];
        __syncthreads();
    }
    float mu = red[0] * (1.f / DD);
    __syncthreads();
    float d0 = v0 - mu, d1 = v1 - mu, d2 = v2 - mu;
    red[tid] = d0 * d0 + d1 * d1 + d2 * d2;
    __syncthreads();
    for (int st = 128; st > 0; st >>= 1) {
        if (tid < st) red[tid] += red[tid + st];
        __syncthreads();
    }
    float inv = rsqrtf(red[0] * (1.f / DD) + 1e-5f);
    onr[tid]       = d0 * inv * w[tid]       + b[tid];
    onr[tid + 256] = d1 * inv * w[tid + 256] + b[tid + 256];
    onr[tid + 512] = d2 * inv * w[tid + 512] + b[tid + 512];
    rr[tid]       += v0;
    rr[tid + 256] += v1;
    rr[tid + 512] += v2;
}

// ---------------------------------------------------------------------------
// Final: out = LayerNorm(x + res)*fw + fb
// ---------------------------------------------------------------------------
__global__ void __launch_bounds__(256)
final_ln_kernel(const float* __restrict__ x, const float* __restrict__ res,
                const float* __restrict__ w, const float* __restrict__ b,
                float* __restrict__ out) {
    int row = blockIdx.x;
    const float* xr = x + (size_t)row * DD;
    const float* rr = res + (size_t)row * DD;
    float* o = out + (size_t)row * DD;
    int tid = threadIdx.x;
    __shared__ float red[256];

    float v0 = xr[tid] + rr[tid];
    float v1 = xr[tid + 256] + rr[tid + 256];
    float v2 = xr[tid + 512] + rr[tid + 512];
    red[tid] = v0 + v1 + v2;
    __syncthreads();
    for (int st = 128; st > 0; st >>= 1) {
        if (tid < st) red[tid] += red[tid + st];
        __syncthreads();
    }
    float mu = red[0] * (1.f / DD);
    __syncthreads();
    float d0 = v0 - mu, d1 = v1 - mu, d2 = v2 - mu;
    red[tid] = d0 * d0 + d1 * d1 + d2 * d2;
    __syncthreads();
    for (int st = 128; st > 0; st >>= 1) {
        if (tid < st) red[tid] += red[tid + st];
        __syncthreads();
    }
    float inv = rsqrtf(red[0] * (1.f / DD) + 1e-5f);
    o[tid]       = d0 * inv * w[tid]       + b[tid];
    o[tid + 256] = d1 * inv * w[tid + 256] + b[tid + 256];
    o[tid + 512] = d2 * inv * w[tid + 512] + b[tid + 512];
}

// ===========================================================================
// Tensor-core GEMM: C[M,N] = A[M,K] * W[N,K]^T  via bf16 hi/lo 3-pass split.
// CTA tile 128x128, BK=32, 256 threads (8 warps: 2 along M x 4 along N),
// warp tile 64x32, mma.sync.m16n8k16 bf16 with fp32 accumulate.
// Requires M%128==0, N%128==0, K%32==0.
// ===========================================================================
__device__ __forceinline__ unsigned smem_u32(const void* p) {
    return (unsigned)__cvta_generic_to_shared(p);
}

__device__ __forceinline__ void ldsm_x4(unsigned* r, unsigned addr) {
    asm volatile("ldmatrix.sync.aligned.m8n8.x4.shared.b16 {%0,%1,%2,%3}, [%4];"
                 : "=r"(r[0]), "=r"(r[1]), "=r"(r[2]), "=r"(r[3]) : "r"(addr));
}

__device__ __forceinline__ void mma_bf16(float* c, const unsigned* a, const unsigned* b) {
    asm volatile(
        "mma.sync.aligned.m16n8k16.row.col.f32.bf16.bf16.f32 "
        "{%0,%1,%2,%3}, {%4,%5,%6,%7}, {%8,%9}, {%0,%1,%2,%3};"
        : "+f"(c[0]), "+f"(c[1]), "+f"(c[2]), "+f"(c[3])
        : "r"(a[0]), "r"(a[1]), "r"(a[2]), "r"(a[3]), "r"(b[0]), "r"(b[1]));
}

constexpr int SP = 40;   // smem row pitch (bf16 elems): 80B -> conflict-free ldmatrix

__global__ void __launch_bounds__(256)
gemm_tc_kernel(const float* __restrict__ A, int lda,
               const float* __restrict__ W,
               float* __restrict__ C, int ldc, int K) {
    __shared__ __nv_bfloat16 Ah[128][SP], Al[128][SP], Wh[128][SP], Wl[128][SP];

    const int tid  = threadIdx.x;
    const int lane = tid & 31;
    const int warp = tid >> 5;
    const int wm = (warp & 1) * 64;
    const int wn = (warp >> 1) * 32;
    const int m0 = blockIdx.y * 128;
    const int n0 = blockIdx.x * 128;

    // global load mapping: thread -> (row, 16-wide k group)
    const int lrow = tid >> 1;
    const int lcg  = (tid & 1) * 16;
    const float* Aptr = A + (size_t)(m0 + lrow) * lda + lcg;
    const float* Wptr = W + (size_t)(n0 + lrow) * K + lcg;

    float acc[4][4][4];
#pragma unroll
    for (int i = 0; i < 4; i++)
#pragma unroll
        for (int j = 0; j < 4; j++)
#pragma unroll
            for (int q = 0; q < 4; q++) acc[i][j][q] = 0.f;

    float4 pa[4], pw[4];

    const int nsteps = K / 32;

    // prologue: load k-block 0
#pragma unroll
    for (int i = 0; i < 4; i++) {
        pa[i] = *(const float4*)(Aptr + i * 4);
        pw[i] = *(const float4*)(Wptr + i * 4);
    }
    // store to smem (hi/lo split)
    {
#pragma unroll
        for (int i = 0; i < 4; i++) {
            int c = lcg + i * 4;
            __nv_bfloat162 ah0 = __floats2bfloat162_rn(pa[i].x, pa[i].y);
            __nv_bfloat162 ah1 = __floats2bfloat162_rn(pa[i].z, pa[i].w);
            __nv_bfloat162 al0 = __floats2bfloat162_rn(pa[i].x - __low2float(ah0),
                                                       pa[i].y - __high2float(ah0));
            __nv_bfloat162 al1 = __floats2bfloat162_rn(pa[i].z - __low2float(ah1),
                                                       pa[i].w - __high2float(ah1));
            *reinterpret_cast<__nv_bfloat162*>(&Ah[lrow][c])     = ah0;
            *reinterpret_cast<__nv_bfloat162*>(&Ah[lrow][c + 2]) = ah1;
            *reinterpret_cast<__nv_bfloat162*>(&Al[lrow][c])     = al0;
            *reinterpret_cast<__nv_bfloat162*>(&Al[lrow][c + 2]) = al1;
            __nv_bfloat162 wh0 = __floats2bfloat162_rn(pw[i].x, pw[i].y);
            __nv_bfloat162 wh1 = __floats2bfloat162_rn(pw[i].z, pw[i].w);
            __nv_bfloat162 wl0 = __floats2bfloat162_rn(pw[i].x - __low2float(wh0),
                                                       pw[i].y - __high2float(wh0));
            __nv_bfloat162 wl1 = __floats2bfloat162_rn(pw[i].z - __low2float(wh1),
                                                       pw[i].w - __high2float(wh1));
            *reinterpret_cast<__nv_bfloat162*>(&Wh[lrow][c])     = wh0;
            *reinterpret_cast<__nv_bfloat162*>(&Wh[lrow][c + 2]) = wh1;
            *reinterpret_cast<__nv_bfloat162*>(&Wl[lrow][c])     = wl0;
            *reinterpret_cast<__nv_bfloat162*>(&Wl[lrow][c + 2]) = wl1;
        }
    }
    __syncthreads();

    for (int s = 0; s < nsteps; s++) {
        // prefetch next k-block into registers
        if (s + 1 < nsteps) {
            const float* ap = Aptr + (s + 1) * 32;
            const float* wp = Wptr + (s + 1) * 32;
#pragma unroll
            for (int i = 0; i < 4; i++) {
                pa[i] = *(const float4*)(ap + i * 4);
                pw[i] = *(const float4*)(wp + i * 4);
            }
        }

        // compute on current smem tile
#pragma unroll
        for (int kk = 0; kk < 32; kk += 16) {
            unsigned af[4][4];
            unsigned whf[4][2], wlf[4][2];
            const int arow = wm + (lane & 7) + (lane & 8);
            const int acol = kk + ((lane >> 4) << 3);
            const int brow = wn + (lane & 7) + ((lane >> 4) << 3);
            const int bcol = kk + (lane & 8);
#pragma unroll
            for (int mi = 0; mi < 4; mi++)
                ldsm_x4(af[mi], smem_u32(&Ah[arow + mi * 16][acol]));
#pragma unroll
            for (int nj = 0; nj < 2; nj++) {
                unsigned r[4];
                ldsm_x4(r, smem_u32(&Wh[brow + nj * 16][bcol]));
                whf[nj * 2][0] = r[0]; whf[nj * 2][1] = r[1];
                whf[nj * 2 + 1][0] = r[2]; whf[nj * 2 + 1][1] = r[3];
                ldsm_x4(r, smem_u32(&Wl[brow + nj * 16][bcol]));
                wlf[nj * 2][0] = r[0]; wlf[nj * 2][1] = r[1];
                wlf[nj * 2 + 1][0] = r[2]; wlf[nj * 2 + 1][1] = r[3];
            }
            // hi*hi + hi*lo
#pragma unroll
            for (int mi = 0; mi < 4; mi++)
#pragma unroll
                for (int ni = 0; ni < 4; ni++) {
                    mma_bf16(acc[mi][ni], af[mi], whf[ni]);
                    mma_bf16(acc[mi][ni], af[mi], wlf[ni]);
                }
            // lo*hi (reload A as lo)
#pragma unroll
            for (int mi = 0; mi < 4; mi++)
                ldsm_x4(af[mi], smem_u32(&Al[arow + mi * 16][acol]));
#pragma unroll
            for (int mi = 0; mi < 4; mi++)
#pragma unroll
                for (int ni = 0; ni < 4; ni++)
                    mma_bf16(acc[mi][ni], af[mi], whf[ni]);
        }
        __syncthreads();

        // store prefetched block for next iteration
        if (s + 1 < nsteps) {
#pragma unroll
            for (int i = 0; i < 4; i++) {
                int c = lcg + i * 4;
                __nv_bfloat162 ah0 = __floats2bfloat162_rn(pa[i].x, pa[i].y);
                __nv_bfloat162 ah1 = __floats2bfloat162_rn(pa[i].z, pa[i].w);
                __nv_bfloat162 al0 = __floats2bfloat162_rn(pa[i].x - __low2float(ah0),
                                                           pa[i].y - __high2float(ah0));
                __nv_bfloat162 al1 = __floats2bfloat162_rn(pa[i].z - __low2float(ah1),
                                                           pa[i].w - __high2float(ah1));
                *reinterpret_cast<__nv_bfloat162*>(&Ah[lrow][c])     = ah0;
                *reinterpret_cast<__nv_bfloat162*>(&Ah[lrow][c + 2]) = ah1;
                *reinterpret_cast<__nv_bfloat162*>(&Al[lrow][c])     = al0;
                *reinterpret_cast<__nv_bfloat162*>(&Al[lrow][c + 2]) = al1;
                __nv_bfloat162 wh0 = __floats2bfloat162_rn(pw[i].x, pw[i].y);
                __nv_bfloat162 wh1 = __floats2bfloat162_rn(pw[i].z, pw[i].w);
                __nv_bfloat162 wl0 = __floats2bfloat162_rn(pw[i].x - __low2float(wh0),
                                                           pw[i].y - __high2float(wh0));
                __nv_bfloat162 wl1 = __floats2bfloat162_rn(pw[i].z - __low2float(wh1),
                                                           pw[i].w - __high2float(wh1));
                *reinterpret_cast<__nv_bfloat162*>(&Wh[lrow][c])     = wh0;
                *reinterpret_cast<__nv_bfloat162*>(&Wh[lrow][c + 2]) = wh1;
                *reinterpret_cast<__nv_bfloat162*>(&Wl[lrow][c])     = wl0;
                *reinterpret_cast<__nv_bfloat162*>(&Wl[lrow][c + 2]) = wl1;
            }
            __syncthreads();
        }
    }

    // epilogue
#pragma unroll
    for (int mi = 0; mi < 4; mi++) {
        int r0 = m0 + wm + mi * 16 + (lane >> 2);
#pragma unroll
        for (int ni = 0; ni < 4; ni++) {
            int c = n0 + wn + ni * 8 + (lane & 3) * 2;
            float2 v0 = make_float2(acc[mi][ni][0], acc[mi][ni][1]);
            float2 v1 = make_float2(acc[mi][ni][2], acc[mi][ni][3]);
            *(float2*)&C[(size_t)r0 * ldc + c] = v0;
            *(float2*)&C[(size_t)(r0 + 8) * ldc + c] = v1;
        }
    }
}

// ---------------------------------------------------------------------------
// Generic tiled fp32 GEMM (kept for the small projections):
// C[m,n] = sum_k A[m,k] * W[n,k]  (+ epilogue)
// BM=128, BN=64, BK=16, 256 threads, 8x4 microtile.
// EPI: 0 = plain store, 1 = bias + softplus.
// ---------------------------------------------------------------------------
template <int EPI>
__global__ void __launch_bounds__(256)
gemm_kernel(const float* __restrict__ A, int lda,
            const float* __restrict__ W,
            const float* __restrict__ bias,
            float* __restrict__ C, int ldc,
            int N, int K) {
    __shared__ float As[16][132];
    __shared__ float Ws[16][68];
    const int tid = threadIdx.x;
    const int tx = tid & 15, ty = tid >> 4;
    const int m0 = blockIdx.y * 128, n0 = blockIdx.x * 64;

    const int ar = tid >> 1;
    const int ak = (tid & 1) * 8;
    const int wr = tid >> 2;
    const int wk = (tid & 3) * 4;

    float acc[8][4];
#pragma unroll
    for (int i = 0; i < 8; i++)
#pragma unroll
        for (int j = 0; j < 4; j++) acc[i][j] = 0.f;

    for (int k0 = 0; k0 < K; k0 += 16) {
        const float* ap = A + (size_t)(m0 + ar) * lda + k0 + ak;
        float4 a0 = *(const float4*)(ap);
        float4 a1 = *(const float4*)(ap + 4);
        As[ak + 0][ar] = a0.x; As[ak + 1][ar] = a0.y;
        As[ak + 2][ar] = a0.z; As[ak + 3][ar] = a0.w;
        As[ak + 4][ar] = a1.x; As[ak + 5][ar] = a1.y;
        As[ak + 6][ar] = a1.z; As[ak + 7][ar] = a1.w;

        float4 wv = make_float4(0.f, 0.f, 0.f, 0.f);
        if (n0 + wr < N)
            wv = *(const float4*)(W + (size_t)(n0 + wr) * K + k0 + wk);
        Ws[wk + 0][wr] = wv.x; Ws[wk + 1][wr] = wv.y;
        Ws[wk + 2][wr] = wv.z; Ws[wk + 3][wr] = wv.w;
        __syncthreads();

#pragma unroll
        for (int kk = 0; kk < 16; kk++) {
            float4 av0 = *(const float4*)(&As[kk][ty * 8]);
            float4 av1 = *(const float4*)(&As[kk][ty * 8 + 4]);
            float4 wv0 = *(const float4*)(&Ws[kk][tx * 4]);
            float a[8] = {av0.x, av0.y, av0.z, av0.w, av1.x, av1.y, av1.z, av1.w};
            float w[4] = {wv0.x, wv0.y, wv0.z, wv0.w};
#pragma unroll
            for (int i = 0; i < 8; i++)
#pragma unroll
                for (int j = 0; j < 4; j++)
                    acc[i][j] += a[i] * w[j];
        }
        __syncthreads();
    }

#pragma unroll
    for (int i = 0; i < 8; i++) {
        int m = m0 + ty * 8 + i;
#pragma unroll
        for (int j = 0; j < 4; j++) {
            int n = n0 + tx * 4 + j;
            if (n < N) {
                float v = acc[i][j];
                if (EPI == 1) {
                    v += bias[n];
                    v = (v > 20.f) ? v : log1pf(__expf(v));
                }
                C[(size_t)m * ldc + n] = v;
            }
        }
    }
}

// ---------------------------------------------------------------------------
// Causal depthwise conv (KC=4, left pad 3) + bias + SiLU.
// ---------------------------------------------------------------------------
__global__ void __launch_bounds__(256)
conv_kernel(const float* __restrict__ xz, float* __restrict__ xc,
            const float* __restrict__ cw, const float* __restrict__ cb) {
    int idx = blockIdx.x * blockDim.x + threadIdx.x;
    if (idx >= TT * DIN) return;
    int c = idx % DIN;
    int tb = idx / DIN;
    int t = tb % LL;
    int b = tb / LL;
    float acc = cb[c];
#pragma unroll
    for (int k = 0; k < KCC; k++) {
        int tt = t - (KCC - 1) + k;
        if (tt >= 0)
            acc += cw[c * KCC + k] * xz[((size_t)(b * LL + tt)) * (2 * DIN) + c];
    }
    float sg = 1.f / (1.f + __expf(-acc));
    xc[idx] = acc * sg;
}

// ---------------------------------------------------------------------------
// Selective scan. Warp = 2 channels x 16 states; thread owns h[b,d,n] scalar.
// ---------------------------------------------------------------------------
__global__ void __launch_bounds__(256)
scan_kernel(const float* __restrict__ dt, const float* __restrict__ xc,
            const float* __restrict__ dbc, const float* __restrict__ xz,
            float* __restrict__ y,
            const float* __restrict__ Alog, const float* __restrict__ Dp) {
    int warp = threadIdx.x >> 5;
    int lane = threadIdx.x & 31;
    int n = lane & 15;
    int dl = lane >> 4;
    constexpr int BLOCKS_PER_B = DIN / 16;   // 96
    int b = blockIdx.x / BLOCKS_PER_B;
    int d = (blockIdx.x % BLOCKS_PER_B) * 16 + warp * 2 + dl;

    float Av = -__expf(Alog[d * NSS + n]);
    float Dv = Dp[d];
    float h = 0.f;
    size_t rowbase = (size_t)b * LL;

    for (int t = 0; t < LL; t++) {
        size_t row = rowbase + t;
        float dtv = dt[row * DIN + d];
        float xv  = xc[row * DIN + d];
        float Bv  = dbc[row * NR + DRR + n];
        float Cv  = dbc[row * NR + DRR + NSS + n];
        float dA  = __expf(dtv * Av);
        h = dA * h + (dtv * xv) * Bv;
        float yp = h * Cv;
        yp += __shfl_xor_sync(0xffffffffu, yp, 8);
        yp += __shfl_xor_sync(0xffffffffu, yp, 4);
        yp += __shfl_xor_sync(0xffffffffu, yp, 2);
        yp += __shfl_xor_sync(0xffffffffu, yp, 1);
        if (n == 0) {
            float zv = xz[row * (2 * DIN) + DIN + d];
            float sg = zv / (1.f + __expf(-zv));
            y[row * DIN + d] = (yp + xv * Dv) * sg;
        }
    }
}

// ---------------------------------------------------------------------------
// Orchestration
// ---------------------------------------------------------------------------
extern "C" void kernel_launch(void* const* d_in, const int* in_sizes, int n_in,
                              void* d_out, int out_size) {
    const float* x        = (const float*)d_in[0];
    const float* ln_w     = (const float*)d_in[1];
    const float* ln_b     = (const float*)d_in[2];
    const float* in_proj  = (const float*)d_in[3];
    const float* conv_w   = (const float*)d_in[4];
    const float* conv_b   = (const float*)d_in[5];
    const float* x_proj   = (const float*)d_in[6];
    const float* dt_w     = (const float*)d_in[7];
    const float* dt_b     = (const float*)d_in[8];
    const float* A_log    = (const float*)d_in[9];
    const float* D_skip   = (const float*)d_in[10];
    const float* out_proj = (const float*)d_in[11];
    const float* fn_w     = (const float*)d_in[12];
    const float* fn_b     = (const float*)d_in[13];
    float* out = (float*)d_out;

    float* base = nullptr;
    cudaGetSymbolAddress((void**)&base, g_buf);
    float* bx   = base + O_X;
    float* bres = base + O_RES;
    float* bxn  = base + O_XN;
    float* bxz  = base + O_XZ;
    float* bxc  = base + O_XC;
    float* bdbc = base + O_DBC;
    float* bdt  = base + O_DT;
    float* by   = base + O_Y;

    init_kernel<<<(TT * DD) / 256, 256>>>(x, bx, bres);

    for (int l = 0; l < NLAY; l++) {
        layer_ln_kernel<<<TT, 256>>>(bx, bres, bxn,
                                     ln_w + (size_t)l * DD, ln_b + (size_t)l * DD);
        // xz = xn @ Wi^T   (2048 x 3072, K=768)  — tensor-core hi/lo bf16
        gemm_tc_kernel<<<dim3((2 * DIN) / 128, TT / 128), 256>>>(
            bxn, DD, in_proj + (size_t)l * 2 * DIN * DD,
            bxz, 2 * DIN, DD);
        // xc = silu(conv(xi) + cb)
        conv_kernel<<<(TT * DIN) / 256, 256>>>(
            bxz, bxc, conv_w + (size_t)l * DIN * KCC, conv_b + (size_t)l * DIN);
        // dbc = xc @ Wx^T  (2048 x 80, K=1536)
        gemm_kernel<0><<<dim3((NR + 63) / 64, TT / 128), 256>>>(
            bxc, DIN, x_proj + (size_t)l * NR * DIN, nullptr,
            bdbc, NR, NR, DIN);
        // dt = softplus(dbc[:, :48] @ Wdt^T + bdt)  (2048 x 1536, K=48)
        gemm_kernel<1><<<dim3(DIN / 64, TT / 128), 256>>>(
            bdbc, NR, dt_w + (size_t)l * DIN * DRR, dt_b + (size_t)l * DIN,
            bdt, DIN, DIN, DRR);
        // selective scan + gating
        scan_kernel<<<BB * (DIN / 16), 256>>>(
            bdt, bxc, bdbc, bxz, by,
            A_log + (size_t)l * DIN * NSS, D_skip + (size_t)l * DIN);
        // x_next = y @ Wo^T  (2048 x 768, K=1536)  — tensor-core hi/lo bf16
        gemm_tc_kernel<<<dim3(DD / 128, TT / 128), 256>>>(
            by, DIN, out_proj + (size_t)l * DD * DIN,
            bx, DD, DIN);
    }

    final_ln_kernel<<<TT, 256>>>(bx, bres, fn_w, fn_b, out);
}

// round 3
// speedup vs baseline: 1.3186x; 1.0368x over previous
#include <cuda_runtime.h>
#include <cuda_bf16.h>
#include <math.h>

// Problem constants
constexpr int BB   = 2;
constexpr int LL   = 1024;
constexpr int DD   = 768;
constexpr int NLAY = 8;
constexpr int DIN  = 1536;       // 2*D
constexpr int NSS  = 16;
constexpr int DRR  = 48;         // D/16
constexpr int KCC  = 4;
constexpr int TT   = BB * LL;    // 2048 tokens
constexpr int NR   = DRR + 2 * NSS;  // 80

// fp32 scratch
constexpr size_t O_X   = 0;
constexpr size_t O_RES = O_X   + (size_t)TT * DD;
constexpr size_t O_XZ  = O_RES + (size_t)TT * DD;
constexpr size_t O_XC  = O_XZ  + (size_t)TT * 2 * DIN;
constexpr size_t O_DBC = O_XC  + (size_t)TT * DIN;
constexpr size_t O_DT  = O_DBC + (size_t)TT * NR;
constexpr size_t O_END = O_DT  + (size_t)TT * DIN;
__device__ float g_buf[O_END];

// bf16 hi/lo activation + weight buffers
constexpr size_t NWI = (size_t)NLAY * 2 * DIN * DD;   // in_proj elems
constexpr size_t NWO = (size_t)NLAY * DD * DIN;       // out_proj elems
__device__ __nv_bfloat16 g_xn_h[(size_t)TT * DD];
__device__ __nv_bfloat16 g_xn_l[(size_t)TT * DD];
__device__ __nv_bfloat16 g_y_h[(size_t)TT * DIN];
__device__ __nv_bfloat16 g_y_l[(size_t)TT * DIN];
__device__ __nv_bfloat16 g_wi_h[NWI];
__device__ __nv_bfloat16 g_wi_l[NWI];
__device__ __nv_bfloat16 g_wo_h[NWO];
__device__ __nv_bfloat16 g_wo_l[NWO];

// ---------------------------------------------------------------------------
// weight conversion: fp32 -> bf16 hi/lo (once per launch, ~28us of bandwidth)
// ---------------------------------------------------------------------------
__global__ void cvt_weights_kernel(const float* __restrict__ wi,
                                   const float* __restrict__ wo) {
    size_t i = (size_t)blockIdx.x * 256 + threadIdx.x;
    if (i < NWI) {
        float v = wi[i];
        __nv_bfloat16 h = __float2bfloat16(v);
        g_wi_h[i] = h;
        g_wi_l[i] = __float2bfloat16(v - __bfloat162float(h));
    } else if (i < NWI + NWO) {
        size_t j = i - NWI;
        float v = wo[j];
        __nv_bfloat16 h = __float2bfloat16(v);
        g_wo_h[j] = h;
        g_wo_l[j] = __float2bfloat16(v - __bfloat162float(h));
    }
}

// ---------------------------------------------------------------------------
// init: x -> scratch, res = 0
// ---------------------------------------------------------------------------
__global__ void init_kernel(const float* __restrict__ xin,
                            float* __restrict__ x, float* __restrict__ res) {
    int i = blockIdx.x * blockDim.x + threadIdx.x;
    if (i < TT * DD) { x[i] = xin[i]; res[i] = 0.f; }
}

// ---------------------------------------------------------------------------
// Per-layer: res += x ; xn = LN(x)*w + b -> bf16 hi/lo   (one block per token)
// ---------------------------------------------------------------------------
__global__ void __launch_bounds__(256)
layer_ln_kernel(const float* __restrict__ x, float* __restrict__ res,
                __nv_bfloat16* __restrict__ xnh, __nv_bfloat16* __restrict__ xnl,
                const float* __restrict__ w, const float* __restrict__ b) {
    int row = blockIdx.x;
    const float* xr = x + (size_t)row * DD;
    float* rr = res + (size_t)row * DD;
    __nv_bfloat16* oh = xnh + (size_t)row * DD;
    __nv_bfloat16* ol = xnl + (size_t)row * DD;
    int tid = threadIdx.x;
    __shared__ float red[256];

    float v0 = xr[tid], v1 = xr[tid + 256], v2 = xr[tid + 512];
    red[tid] = v0 + v1 + v2;
    __syncthreads();
    for (int st = 128; st > 0; st >>= 1) {
        if (tid < st) red[tid] += red[tid + st];
        __syncthreads();
    }
    float mu = red[0] * (1.f / DD);
    __syncthreads();
    float d0 = v0 - mu, d1 = v1 - mu, d2 = v2 - mu;
    red[tid] = d0 * d0 + d1 * d1 + d2 * d2;
    __syncthreads();
    for (int st = 128; st > 0; st >>= 1) {
        if (tid < st) red[tid] += red[tid + st];
        __syncthreads();
    }
    float inv = rsqrtf(red[0] * (1.f / DD) + 1e-5f);
#pragma unroll
    for (int c = 0; c < 3; c++) {
        int i = tid + c * 256;
        float dv = (c == 0 ? d0 : c == 1 ? d1 : d2);
        float v = dv * inv * w[i] + b[i];
        __nv_bfloat16 h = __float2bfloat16(v);
        oh[i] = h;
        ol[i] = __float2bfloat16(v - __bfloat162float(h));
    }
    rr[tid]       += v0;
    rr[tid + 256] += v1;
    rr[tid + 512] += v2;
}

// ---------------------------------------------------------------------------
// Final: out = LayerNorm(x + res)*fw + fb
// ---------------------------------------------------------------------------
__global__ void __launch_bounds__(256)
final_ln_kernel(const float* __restrict__ x, const float* __restrict__ res,
                const float* __restrict__ w, const float* __restrict__ b,
                float* __restrict__ out) {
    int row = blockIdx.x;
    const float* xr = x + (size_t)row * DD;
    const float* rr = res + (size_t)row * DD;
    float* o = out + (size_t)row * DD;
    int tid = threadIdx.x;
    __shared__ float red[256];

    float v0 = xr[tid] + rr[tid];
    float v1 = xr[tid + 256] + rr[tid + 256];
    float v2 = xr[tid + 512] + rr[tid + 512];
    red[tid] = v0 + v1 + v2;
    __syncthreads();
    for (int st = 128; st > 0; st >>= 1) {
        if (tid < st) red[tid] += red[tid + st];
        __syncthreads();
    }
    float mu = red[0] * (1.f / DD);
    __syncthreads();
    float d0 = v0 - mu, d1 = v1 - mu, d2 = v2 - mu;
    red[tid] = d0 * d0 + d1 * d1 + d2 * d2;
    __syncthreads();
    for (int st = 128; st > 0; st >>= 1) {
        if (tid < st) red[tid] += red[tid + st];
        __syncthreads();
    }
    float inv = rsqrtf(red[0] * (1.f / DD) + 1e-5f);
    o[tid]       = d0 * inv * w[tid]       + b[tid];
    o[tid + 256] = d1 * inv * w[tid + 256] + b[tid + 256];
    o[tid + 512] = d2 * inv * w[tid + 512] + b[tid + 512];
}

// ===========================================================================
// Tensor-core GEMM (bf16 hi/lo, 3-pass): C[M,N] = A[M,K] * W[N,K]^T, fp32 C.
// CTA tile 128x128, BK=32, 256 threads (8 warps: 2M x 4N), warp tile 64x32.
// Double-buffered cp.async, XOR-swizzled 64B-pitch smem. M,N %128, K %32.
// ===========================================================================
__device__ __forceinline__ unsigned smem_u32(const void* p) {
    return (unsigned)__cvta_generic_to_shared(p);
}
__device__ __forceinline__ unsigned swz(int r, int c) {
    // row r (0..127), element col c (multiple of 8); 64B pitch, 16B chunks.
    return (unsigned)(r * 64) + ((((unsigned)c >> 3) ^ (((unsigned)r >> 1) & 3u)) << 4);
}
__device__ __forceinline__ void ldsm_x4(unsigned* r, unsigned addr) {
    asm volatile("ldmatrix.sync.aligned.m8n8.x4.shared.b16 {%0,%1,%2,%3}, [%4];"
                 : "=r"(r[0]), "=r"(r[1]), "=r"(r[2]), "=r"(r[3]) : "r"(addr));
}
__device__ __forceinline__ void mma_bf16(float* c, const unsigned* a, const unsigned* b) {
    asm volatile(
        "mma.sync.aligned.m16n8k16.row.col.f32.bf16.bf16.f32 "
        "{%0,%1,%2,%3}, {%4,%5,%6,%7}, {%8,%9}, {%0,%1,%2,%3};"
        : "+f"(c[0]), "+f"(c[1]), "+f"(c[2]), "+f"(c[3])
        : "r"(a[0]), "r"(a[1]), "r"(a[2]), "r"(a[3]), "r"(b[0]), "r"(b[1]));
}
__device__ __forceinline__ void cp16(unsigned dst, const void* src) {
    asm volatile("cp.async.cg.shared.global [%0], [%1], 16;" :: "r"(dst), "l"(src));
}

constexpr int STAGE_BYTES = 32768;          // 4 arrays x 8KB
constexpr int ARR_A_H = 0, ARR_A_L = 8192, ARR_W_H = 16384, ARR_W_L = 24576;

__global__ void __launch_bounds__(256)
gemm_tc2_kernel(const __nv_bfloat16* __restrict__ Ahg,
                const __nv_bfloat16* __restrict__ Alg,
                const __nv_bfloat16* __restrict__ Whg,
                const __nv_bfloat16* __restrict__ Wlg,
                float* __restrict__ C, int ldc, int K) {
    extern __shared__ __align__(16) unsigned char smraw[];
    const unsigned sbase = smem_u32(smraw);

    const int tid  = threadIdx.x;
    const int lane = tid & 31;
    const int warp = tid >> 5;
    const int wm = (warp & 1) * 64;
    const int wn = (warp >> 1) * 32;
    const int m0 = blockIdx.y * 128;
    const int n0 = blockIdx.x * 128;

    // loader mapping: thread -> row = tid>>1, two 16B chunks (q = (tid&1)*2 + i)
    const int lrow = tid >> 1;
    const int lq0  = (tid & 1) * 2;
    const size_t aoff = (size_t)(m0 + lrow) * K;
    const size_t woff = (size_t)(n0 + lrow) * K;
    const unsigned sdst0 = (unsigned)(lrow * 64) +
                           (((unsigned)lq0 ^ (((unsigned)lrow >> 1) & 3u)) << 4);
    const unsigned sdst1 = (unsigned)(lrow * 64) +
                           ((((unsigned)lq0 + 1u) ^ (((unsigned)lrow >> 1) & 3u)) << 4);

    const int nsteps = K / 32;

    auto load_stage = [&](int buf, int k0) {
        unsigned sb = sbase + buf * STAGE_BYTES;
        const __nv_bfloat16* pa_h = Ahg + aoff + k0 + lq0 * 8;
        const __nv_bfloat16* pa_l = Alg + aoff + k0 + lq0 * 8;
        const __nv_bfloat16* pw_h = Whg + woff + k0 + lq0 * 8;
        const __nv_bfloat16* pw_l = Wlg + woff + k0 + lq0 * 8;
        cp16(sb + ARR_A_H + sdst0, pa_h);
        cp16(sb + ARR_A_H + sdst1, pa_h + 8);
        cp16(sb + ARR_A_L + sdst0, pa_l);
        cp16(sb + ARR_A_L + sdst1, pa_l + 8);
        cp16(sb + ARR_W_H + sdst0, pw_h);
        cp16(sb + ARR_W_H + sdst1, pw_h + 8);
        cp16(sb + ARR_W_L + sdst0, pw_l);
        cp16(sb + ARR_W_L + sdst1, pw_l + 8);
    };

    float acc[4][4][4];
#pragma unroll
    for (int i = 0; i < 4; i++)
#pragma unroll
        for (int j = 0; j < 4; j++)
#pragma unroll
            for (int q = 0; q < 4; q++) acc[i][j][q] = 0.f;

    load_stage(0, 0);
    asm volatile("cp.async.commit_group;");
    load_stage(1, 32);
    asm volatile("cp.async.commit_group;");
    asm volatile("cp.async.wait_group 1;");
    __syncthreads();

    const int arow = wm + (lane & 7) + (lane & 8);
    const int brow = wn + (lane & 7) + ((lane >> 4) << 3);

    for (int s = 0; s < nsteps; s++) {
        const int buf = s & 1;
        const unsigned sb = sbase + buf * STAGE_BYTES;
#pragma unroll
        for (int kk = 0; kk < 32; kk += 16) {
            const int acol = kk + ((lane >> 4) << 3);
            const int bcol = kk + (lane & 8);
            unsigned af[4][4];
            unsigned whf[4][2], wlf[4][2];
#pragma unroll
            for (int mi = 0; mi < 4; mi++)
                ldsm_x4(af[mi], sb + ARR_A_H + swz(arow + mi * 16, acol));
#pragma unroll
            for (int nj = 0; nj < 2; nj++) {
                unsigned r[4];
                ldsm_x4(r, sb + ARR_W_H + swz(brow + nj * 16, bcol));
                whf[nj * 2][0] = r[0]; whf[nj * 2][1] = r[1];
                whf[nj * 2 + 1][0] = r[2]; whf[nj * 2 + 1][1] = r[3];
                ldsm_x4(r, sb + ARR_W_L + swz(brow + nj * 16, bcol));
                wlf[nj * 2][0] = r[0]; wlf[nj * 2][1] = r[1];
                wlf[nj * 2 + 1][0] = r[2]; wlf[nj * 2 + 1][1] = r[3];
            }
#pragma unroll
            for (int mi = 0; mi < 4; mi++)
#pragma unroll
                for (int ni = 0; ni < 4; ni++) {
                    mma_bf16(acc[mi][ni], af[mi], whf[ni]);
                    mma_bf16(acc[mi][ni], af[mi], wlf[ni]);
                }
#pragma unroll
            for (int mi = 0; mi < 4; mi++)
                ldsm_x4(af[mi], sb + ARR_A_L + swz(arow + mi * 16, acol));
#pragma unroll
            for (int mi = 0; mi < 4; mi++)
#pragma unroll
                for (int ni = 0; ni < 4; ni++)
                    mma_bf16(acc[mi][ni], af[mi], whf[ni]);
        }
        __syncthreads();                 // everyone done reading buf
        if (s + 2 < nsteps) load_stage(buf, (s + 2) * 32);
        asm volatile("cp.async.commit_group;");
        asm volatile("cp.async.wait_group 1;");   // stage s+1 resident
        __syncthreads();
    }

    // epilogue
#pragma unroll
    for (int mi = 0; mi < 4; mi++) {
        int r0 = m0 + wm + mi * 16 + (lane >> 2);
#pragma unroll
        for (int ni = 0; ni < 4; ni++) {
            int c = n0 + wn + ni * 8 + (lane & 3) * 2;
            *(float2*)&C[(size_t)r0 * ldc + c] =
                make_float2(acc[mi][ni][0], acc[mi][ni][1]);
            *(float2*)&C[(size_t)(r0 + 8) * ldc + c] =
                make_float2(acc[mi][ni][2], acc[mi][ni][3]);
        }
    }
}

// ---------------------------------------------------------------------------
// x_proj SIMT GEMM: dbc[TT,80] = xc[TT,DIN] @ Wx[80,DIN]^T
// BM=64, BN=16, BK=16, 256 threads, 4x1 microtile. Grid (5, 32) = 160 CTAs.
// ---------------------------------------------------------------------------
__global__ void __launch_bounds__(256)
gemm_xproj_kernel(const float* __restrict__ A, const float* __restrict__ W,
                  float* __restrict__ C) {
    __shared__ float As[16][68];
    __shared__ float Ws[16][17];
    const int tid = threadIdx.x;
    const int tx = tid & 15, ty = tid >> 4;
    const int m0 = blockIdx.y * 64, n0 = blockIdx.x * 16;
    const int lrow = tid >> 2;          // 0..63
    const int lq = (tid & 3) * 4;

    float acc[4] = {0.f, 0.f, 0.f, 0.f};

    for (int k0 = 0; k0 < DIN; k0 += 16) {
        float4 av = *(const float4*)(A + (size_t)(m0 + lrow) * DIN + k0 + lq);
        As[lq + 0][lrow] = av.x; As[lq + 1][lrow] = av.y;
        As[lq + 2][lrow] = av.z; As[lq + 3][lrow] = av.w;
        if (tid < 64) {
            int wr = tid >> 2, wq = (tid & 3) * 4;
            float4 wv = *(const float4*)(W + (size_t)(n0 + wr) * DIN + k0 + wq);
            Ws[wq + 0][wr] = wv.x; Ws[wq + 1][wr] = wv.y;
            Ws[wq + 2][wr] = wv.z; Ws[wq + 3][wr] = wv.w;
        }
        __syncthreads();
#pragma unroll
        for (int kk = 0; kk < 16; kk++) {
            float4 a = *(const float4*)(&As[kk][ty * 4]);
            float wv = Ws[kk][tx];
            acc[0] += a.x * wv; acc[1] += a.y * wv;
            acc[2] += a.z * wv; acc[3] += a.w * wv;
        }
        __syncthreads();
    }
#pragma unroll
    for (int i = 0; i < 4; i++)
        C[(size_t)(m0 + ty * 4 + i) * NR + n0 + tx] = acc[i];
}

// ---------------------------------------------------------------------------
// dt GEMM (SIMT, K=48): dt = softplus(dbc[:,:48] @ Wdt^T + bdt)
// BM=128, BN=64, BK=16, 256 threads, 8x4 microtile.
// ---------------------------------------------------------------------------
__global__ void __launch_bounds__(256)
gemm_dt_kernel(const float* __restrict__ A, int lda,
               const float* __restrict__ W,
               const float* __restrict__ bias,
               float* __restrict__ C, int ldc, int N, int K) {
    __shared__ float As[16][132];
    __shared__ float Ws[16][68];
    const int tid = threadIdx.x;
    const int tx = tid & 15, ty = tid >> 4;
    const int m0 = blockIdx.y * 128, n0 = blockIdx.x * 64;
    const int ar = tid >> 1;
    const int ak = (tid & 1) * 8;
    const int wr = tid >> 2;
    const int wk = (tid & 3) * 4;

    float acc[8][4];
#pragma unroll
    for (int i = 0; i < 8; i++)
#pragma unroll
        for (int j = 0; j < 4; j++) acc[i][j] = 0.f;

    for (int k0 = 0; k0 < K; k0 += 16) {
        const float* ap = A + (size_t)(m0 + ar) * lda + k0 + ak;
        float4 a0 = *(const float4*)(ap);
        float4 a1 = *(const float4*)(ap + 4);
        As[ak + 0][ar] = a0.x; As[ak + 1][ar] = a0.y;
        As[ak + 2][ar] = a0.z; As[ak + 3][ar] = a0.w;
        As[ak + 4][ar] = a1.x; As[ak + 5][ar] = a1.y;
        As[ak + 6][ar] = a1.z; As[ak + 7][ar] = a1.w;
        float4 wv = *(const float4*)(W + (size_t)(n0 + wr) * K + k0 + wk);
        Ws[wk + 0][wr] = wv.x; Ws[wk + 1][wr] = wv.y;
        Ws[wk + 2][wr] = wv.z; Ws[wk + 3][wr] = wv.w;
        __syncthreads();
#pragma unroll
        for (int kk = 0; kk < 16; kk++) {
            float4 av0 = *(const float4*)(&As[kk][ty * 8]);
            float4 av1 = *(const float4*)(&As[kk][ty * 8 + 4]);
            float4 wv0 = *(const float4*)(&Ws[kk][tx * 4]);
            float a[8] = {av0.x, av0.y, av0.z, av0.w, av1.x, av1.y, av1.z, av1.w};
            float w[4] = {wv0.x, wv0.y, wv0.z, wv0.w};
#pragma unroll
            for (int i = 0; i < 8; i++)
#pragma unroll
                for (int j = 0; j < 4; j++)
                    acc[i][j] += a[i] * w[j];
        }
        __syncthreads();
    }
#pragma unroll
    for (int i = 0; i < 8; i++) {
        int m = m0 + ty * 8 + i;
#pragma unroll
        for (int j = 0; j < 4; j++) {
            int n = n0 + tx * 4 + j;
            float v = acc[i][j] + bias[n];
            v = (v > 20.f) ? v : log1pf(__expf(v));
            C[(size_t)m * ldc + n] = v;
        }
    }
}

// ---------------------------------------------------------------------------
// Causal depthwise conv (KC=4, left pad 3) + bias + SiLU.
// ---------------------------------------------------------------------------
__global__ void __launch_bounds__(256)
conv_kernel(const float* __restrict__ xz, float* __restrict__ xc,
            const float* __restrict__ cw, const float* __restrict__ cb) {
    int idx = blockIdx.x * blockDim.x + threadIdx.x;
    if (idx >= TT * DIN) return;
    int c = idx % DIN;
    int tb = idx / DIN;
    int t = tb % LL;
    int b = tb / LL;
    float acc = cb[c];
#pragma unroll
    for (int k = 0; k < KCC; k++) {
        int tt = t - (KCC - 1) + k;
        if (tt >= 0)
            acc += cw[c * KCC + k] * xz[((size_t)(b * LL + tt)) * (2 * DIN) + c];
    }
    float sg = 1.f / (1.f + __expf(-acc));
    xc[idx] = acc * sg;
}

// ---------------------------------------------------------------------------
// Selective scan; emits y as bf16 hi/lo for the TC out_proj.
// ---------------------------------------------------------------------------
__global__ void __launch_bounds__(256)
scan_kernel(const float* __restrict__ dt, const float* __restrict__ xc,
            const float* __restrict__ dbc, const float* __restrict__ xz,
            __nv_bfloat16* __restrict__ yh, __nv_bfloat16* __restrict__ yl,
            const float* __restrict__ Alog, const float* __restrict__ Dp) {
    int warp = threadIdx.x >> 5;
    int lane = threadIdx.x & 31;
    int n = lane & 15;
    int dl = lane >> 4;
    constexpr int BLOCKS_PER_B = DIN / 16;   // 96
    int b = blockIdx.x / BLOCKS_PER_B;
    int d = (blockIdx.x % BLOCKS_PER_B) * 16 + warp * 2 + dl;

    float Av = -__expf(Alog[d * NSS + n]);
    float Dv = Dp[d];
    float h = 0.f;
    size_t rowbase = (size_t)b * LL;

    for (int t = 0; t < LL; t++) {
        size_t row = rowbase + t;
        float dtv = dt[row * DIN + d];
        float xv  = xc[row * DIN + d];
        float Bv  = dbc[row * NR + DRR + n];
        float Cv  = dbc[row * NR + DRR + NSS + n];
        float dA  = __expf(dtv * Av);
        h = dA * h + (dtv * xv) * Bv;
        float yp = h * Cv;
        yp += __shfl_xor_sync(0xffffffffu, yp, 8);
        yp += __shfl_xor_sync(0xffffffffu, yp, 4);
        yp += __shfl_xor_sync(0xffffffffu, yp, 2);
        yp += __shfl_xor_sync(0xffffffffu, yp, 1);
        if (n == 0) {
            float zv = xz[row * (2 * DIN) + DIN + d];
            float sg = zv / (1.f + __expf(-zv));
            float g = (yp + xv * Dv) * sg;
            __nv_bfloat16 gh = __float2bfloat16(g);
            yh[row * DIN + d] = gh;
            yl[row * DIN + d] = __float2bfloat16(g - __bfloat162float(gh));
        }
    }
}

// ---------------------------------------------------------------------------
// Orchestration
// ---------------------------------------------------------------------------
extern "C" void kernel_launch(void* const* d_in, const int* in_sizes, int n_in,
                              void* d_out, int out_size) {
    const float* x        = (const float*)d_in[0];
    const float* ln_w     = (const float*)d_in[1];
    const float* ln_b     = (const float*)d_in[2];
    const float* in_proj  = (const float*)d_in[3];
    const float* conv_w   = (const float*)d_in[4];
    const float* conv_b   = (const float*)d_in[5];
    const float* x_proj   = (const float*)d_in[6];
    const float* dt_w     = (const float*)d_in[7];
    const float* dt_b     = (const float*)d_in[8];
    const float* A_log    = (const float*)d_in[9];
    const float* D_skip   = (const float*)d_in[10];
    const float* out_proj = (const float*)d_in[11];
    const float* fn_w     = (const float*)d_in[12];
    const float* fn_b     = (const float*)d_in[13];
    float* out = (float*)d_out;

    float* base = nullptr;
    cudaGetSymbolAddress((void**)&base, g_buf);
    float* bx   = base + O_X;
    float* bres = base + O_RES;
    float* bxz  = base + O_XZ;
    float* bxc  = base + O_XC;
    float* bdbc = base + O_DBC;
    float* bdt  = base + O_DT;

    __nv_bfloat16 *xnh, *xnl, *yh, *yl, *wih, *wil, *woh, *wol;
    cudaGetSymbolAddress((void**)&xnh, g_xn_h);
    cudaGetSymbolAddress((void**)&xnl, g_xn_l);
    cudaGetSymbolAddress((void**)&yh,  g_y_h);
    cudaGetSymbolAddress((void**)&yl,  g_y_l);
    cudaGetSymbolAddress((void**)&wih, g_wi_h);
    cudaGetSymbolAddress((void**)&wil, g_wi_l);
    cudaGetSymbolAddress((void**)&woh, g_wo_h);
    cudaGetSymbolAddress((void**)&wol, g_wo_l);

    cudaFuncSetAttribute(gemm_tc2_kernel,
                         cudaFuncAttributeMaxDynamicSharedMemorySize,
                         2 * STAGE_BYTES);

    cvt_weights_kernel<<<(unsigned)((NWI + NWO + 255) / 256), 256>>>(in_proj, out_proj);
    init_kernel<<<(TT * DD) / 256, 256>>>(x, bx, bres);

    for (int l = 0; l < NLAY; l++) {
        layer_ln_kernel<<<TT, 256>>>(bx, bres, xnh, xnl,
                                     ln_w + (size_t)l * DD, ln_b + (size_t)l * DD);
        // xz = xn @ Wi^T   (2048 x 3072, K=768)
        gemm_tc2_kernel<<<dim3((2 * DIN) / 128, TT / 128), 256, 2 * STAGE_BYTES>>>(
            xnh, xnl,
            wih + (size_t)l * 2 * DIN * DD, wil + (size_t)l * 2 * DIN * DD,
            bxz, 2 * DIN, DD);
        // xc = silu(conv(xi) + cb)
        conv_kernel<<<(TT * DIN) / 256, 256>>>(
            bxz, bxc, conv_w + (size_t)l * DIN * KCC, conv_b + (size_t)l * DIN);
        // dbc = xc @ Wx^T  (2048 x 80, K=1536)
        gemm_xproj_kernel<<<dim3(NR / 16, TT / 64), 256>>>(
            bxc, x_proj + (size_t)l * NR * DIN, bdbc);
        // dt = softplus(dbc[:, :48] @ Wdt^T + bdt)
        gemm_dt_kernel<<<dim3(DIN / 64, TT / 128), 256>>>(
            bdbc, NR, dt_w + (size_t)l * DIN * DRR, dt_b + (size_t)l * DIN,
            bdt, DIN, DIN, DRR);
        // selective scan + gating -> y hi/lo
        scan_kernel<<<BB * (DIN / 16), 256>>>(
            bdt, bxc, bdbc, bxz, yh, yl,
            A_log + (size_t)l * DIN * NSS, D_skip + (size_t)l * DIN);
        // x_next = y @ Wo^T  (2048 x 768, K=1536)
        gemm_tc2_kernel<<<dim3(DD / 128, TT / 128), 256, 2 * STAGE_BYTES>>>(
            yh, yl,
            woh + (size_t)l * DD * DIN, wol + (size_t)l * DD * DIN,
            bx, DD, DIN);
    }

    final_ln_kernel<<<TT, 256>>>(bx, bres, fn_w, fn_b, out);
}

// round 4
// speedup vs baseline: 2.5916x; 1.9654x over previous
#include <cuda_runtime.h>
#include <cuda_bf16.h>
#include <math.h>

// Problem constants
constexpr int BB   = 2;
constexpr int LL   = 1024;
constexpr int DD   = 768;
constexpr int NLAY = 8;
constexpr int DIN  = 1536;       // 2*D
constexpr int NSS  = 16;
constexpr int DRR  = 48;         // D/16
constexpr int KCC  = 4;
constexpr int TT   = BB * LL;    // 2048 tokens
constexpr int NR   = DRR + 2 * NSS;  // 80

// Chunked scan
constexpr int CH = 8;            // chunks
constexpr int CS = LL / CH;      // 128 steps per chunk
constexpr int NSTATE = BB * DIN * NSS;   // 49152

// fp32 scratch
constexpr size_t O_X   = 0;
constexpr size_t O_RES = O_X   + (size_t)TT * DD;
constexpr size_t O_XZ  = O_RES + (size_t)TT * DD;
constexpr size_t O_XC  = O_XZ  + (size_t)TT * 2 * DIN;
constexpr size_t O_DBC = O_XC  + (size_t)TT * DIN;
constexpr size_t O_DT  = O_DBC + (size_t)TT * NR;
constexpr size_t O_END = O_DT  + (size_t)TT * DIN;
__device__ float g_buf[O_END];

// chunked-scan state
__device__ float g_hend[(size_t)CH * NSTATE];
__device__ float g_P[(size_t)CH * NSTATE];
__device__ float g_hinit[(size_t)CH * NSTATE];

// bf16 hi/lo activation + weight buffers
constexpr size_t NWI = (size_t)NLAY * 2 * DIN * DD;   // in_proj elems
constexpr size_t NWO = (size_t)NLAY * DD * DIN;       // out_proj elems
__device__ __nv_bfloat16 g_xn_h[(size_t)TT * DD];
__device__ __nv_bfloat16 g_xn_l[(size_t)TT * DD];
__device__ __nv_bfloat16 g_y_h[(size_t)TT * DIN];
__device__ __nv_bfloat16 g_y_l[(size_t)TT * DIN];
__device__ __nv_bfloat16 g_wi_h[NWI];
__device__ __nv_bfloat16 g_wi_l[NWI];
__device__ __nv_bfloat16 g_wo_h[NWO];
__device__ __nv_bfloat16 g_wo_l[NWO];

// ---------------------------------------------------------------------------
// weight conversion: fp32 -> bf16 hi/lo (once per launch)
// ---------------------------------------------------------------------------
__global__ void cvt_weights_kernel(const float* __restrict__ wi,
                                   const float* __restrict__ wo) {
    size_t i = (size_t)blockIdx.x * 256 + threadIdx.x;
    if (i < NWI) {
        float v = wi[i];
        __nv_bfloat16 h = __float2bfloat16(v);
        g_wi_h[i] = h;
        g_wi_l[i] = __float2bfloat16(v - __bfloat162float(h));
    } else if (i < NWI + NWO) {
        size_t j = i - NWI;
        float v = wo[j];
        __nv_bfloat16 h = __float2bfloat16(v);
        g_wo_h[j] = h;
        g_wo_l[j] = __float2bfloat16(v - __bfloat162float(h));
    }
}

// ---------------------------------------------------------------------------
// init: x -> scratch, res = 0
// ---------------------------------------------------------------------------
__global__ void init_kernel(const float* __restrict__ xin,
                            float* __restrict__ x, float* __restrict__ res) {
    int i = blockIdx.x * blockDim.x + threadIdx.x;
    if (i < TT * DD) { x[i] = xin[i]; res[i] = 0.f; }
}

// ---------------------------------------------------------------------------
// Per-layer: res += x ; xn = LN(x)*w + b -> bf16 hi/lo   (one block per token)
// ---------------------------------------------------------------------------
__global__ void __launch_bounds__(256)
layer_ln_kernel(const float* __restrict__ x, float* __restrict__ res,
                __nv_bfloat16* __restrict__ xnh, __nv_bfloat16* __restrict__ xnl,
                const float* __restrict__ w, const float* __restrict__ b) {
    int row = blockIdx.x;
    const float* xr = x + (size_t)row * DD;
    float* rr = res + (size_t)row * DD;
    __nv_bfloat16* oh = xnh + (size_t)row * DD;
    __nv_bfloat16* ol = xnl + (size_t)row * DD;
    int tid = threadIdx.x;
    __shared__ float red[256];

    float v0 = xr[tid], v1 = xr[tid + 256], v2 = xr[tid + 512];
    red[tid] = v0 + v1 + v2;
    __syncthreads();
    for (int st = 128; st > 0; st >>= 1) {
        if (tid < st) red[tid] += red[tid + st];
        __syncthreads();
    }
    float mu = red[0] * (1.f / DD);
    __syncthreads();
    float d0 = v0 - mu, d1 = v1 - mu, d2 = v2 - mu;
    red[tid] = d0 * d0 + d1 * d1 + d2 * d2;
    __syncthreads();
    for (int st = 128; st > 0; st >>= 1) {
        if (tid < st) red[tid] += red[tid + st];
        __syncthreads();
    }
    float inv = rsqrtf(red[0] * (1.f / DD) + 1e-5f);
#pragma unroll
    for (int c = 0; c < 3; c++) {
        int i = tid + c * 256;
        float dv = (c == 0 ? d0 : c == 1 ? d1 : d2);
        float v = dv * inv * w[i] + b[i];
        __nv_bfloat16 h = __float2bfloat16(v);
        oh[i] = h;
        ol[i] = __float2bfloat16(v - __bfloat162float(h));
    }
    rr[tid]       += v0;
    rr[tid + 256] += v1;
    rr[tid + 512] += v2;
}

// ---------------------------------------------------------------------------
// Final: out = LayerNorm(x + res)*fw + fb
// ---------------------------------------------------------------------------
__global__ void __launch_bounds__(256)
final_ln_kernel(const float* __restrict__ x, const float* __restrict__ res,
                const float* __restrict__ w, const float* __restrict__ b,
                float* __restrict__ out) {
    int row = blockIdx.x;
    const float* xr = x + (size_t)row * DD;
    const float* rr = res + (size_t)row * DD;
    float* o = out + (size_t)row * DD;
    int tid = threadIdx.x;
    __shared__ float red[256];

    float v0 = xr[tid] + rr[tid];
    float v1 = xr[tid + 256] + rr[tid + 256];
    float v2 = xr[tid + 512] + rr[tid + 512];
    red[tid] = v0 + v1 + v2;
    __syncthreads();
    for (int st = 128; st > 0; st >>= 1) {
        if (tid < st) red[tid] += red[tid + st];
        __syncthreads();
    }
    float mu = red[0] * (1.f / DD);
    __syncthreads();
    float d0 = v0 - mu, d1 = v1 - mu, d2 = v2 - mu;
    red[tid] = d0 * d0 + d1 * d1 + d2 * d2;
    __syncthreads();
    for (int st = 128; st > 0; st >>= 1) {
        if (tid < st) red[tid] += red[tid + st];
        __syncthreads();
    }
    float inv = rsqrtf(red[0] * (1.f / DD) + 1e-5f);
    o[tid]       = d0 * inv * w[tid]       + b[tid];
    o[tid + 256] = d1 * inv * w[tid + 256] + b[tid + 256];
    o[tid + 512] = d2 * inv * w[tid + 512] + b[tid + 512];
}

// ===========================================================================
// Tensor-core GEMM (bf16 hi/lo, 3-pass): C[M,N] = A[M,K] * W[N,K]^T, fp32 C.
// CTA tile 128x128, BK=32, 256 threads (8 warps: 2M x 4N), warp tile 64x32.
// 3-stage cp.async pipeline, one __syncthreads per k-step,
// XOR-swizzled 64B-pitch smem. M,N %128, K %32.
// ===========================================================================
__device__ __forceinline__ unsigned smem_u32(const void* p) {
    return (unsigned)__cvta_generic_to_shared(p);
}
__device__ __forceinline__ unsigned swz(int r, int c) {
    return (unsigned)(r * 64) + ((((unsigned)c >> 3) ^ (((unsigned)r >> 1) & 3u)) << 4);
}
__device__ __forceinline__ void ldsm_x4(unsigned* r, unsigned addr) {
    asm volatile("ldmatrix.sync.aligned.m8n8.x4.shared.b16 {%0,%1,%2,%3}, [%4];"
                 : "=r"(r[0]), "=r"(r[1]), "=r"(r[2]), "=r"(r[3]) : "r"(addr));
}
__device__ __forceinline__ void mma_bf16(float* c, const unsigned* a, const unsigned* b) {
    asm volatile(
        "mma.sync.aligned.m16n8k16.row.col.f32.bf16.bf16.f32 "
        "{%0,%1,%2,%3}, {%4,%5,%6,%7}, {%8,%9}, {%0,%1,%2,%3};"
        : "+f"(c[0]), "+f"(c[1]), "+f"(c[2]), "+f"(c[3])
        : "r"(a[0]), "r"(a[1]), "r"(a[2]), "r"(a[3]), "r"(b[0]), "r"(b[1]));
}
__device__ __forceinline__ void cp16(unsigned dst, const void* src) {
    asm volatile("cp.async.cg.shared.global [%0], [%1], 16;" :: "r"(dst), "l"(src));
}

constexpr int STAGE_BYTES = 32768;          // 4 arrays x 8KB
constexpr int NSTAGE = 3;
constexpr int ARR_A_H = 0, ARR_A_L = 8192, ARR_W_H = 16384, ARR_W_L = 24576;

__global__ void __launch_bounds__(256)
gemm_tc2_kernel(const __nv_bfloat16* __restrict__ Ahg,
                const __nv_bfloat16* __restrict__ Alg,
                const __nv_bfloat16* __restrict__ Whg,
                const __nv_bfloat16* __restrict__ Wlg,
                float* __restrict__ C, int ldc, int K) {
    extern __shared__ __align__(16) unsigned char smraw[];
    const unsigned sbase = smem_u32(smraw);

    const int tid  = threadIdx.x;
    const int lane = tid & 31;
    const int warp = tid >> 5;
    const int wm = (warp & 1) * 64;
    const int wn = (warp >> 1) * 32;
    const int m0 = blockIdx.y * 128;
    const int n0 = blockIdx.x * 128;

    const int lrow = tid >> 1;
    const int lq0  = (tid & 1) * 2;
    const size_t aoff = (size_t)(m0 + lrow) * K;
    const size_t woff = (size_t)(n0 + lrow) * K;
    const unsigned sdst0 = (unsigned)(lrow * 64) +
                           (((unsigned)lq0 ^ (((unsigned)lrow >> 1) & 3u)) << 4);
    const unsigned sdst1 = (unsigned)(lrow * 64) +
                           ((((unsigned)lq0 + 1u) ^ (((unsigned)lrow >> 1) & 3u)) << 4);

    const int nsteps = K / 32;

    auto load_stage = [&](int buf, int k0) {
        unsigned sb = sbase + buf * STAGE_BYTES;
        const __nv_bfloat16* pa_h = Ahg + aoff + k0 + lq0 * 8;
        const __nv_bfloat16* pa_l = Alg + aoff + k0 + lq0 * 8;
        const __nv_bfloat16* pw_h = Whg + woff + k0 + lq0 * 8;
        const __nv_bfloat16* pw_l = Wlg + woff + k0 + lq0 * 8;
        cp16(sb + ARR_A_H + sdst0, pa_h);
        cp16(sb + ARR_A_H + sdst1, pa_h + 8);
        cp16(sb + ARR_A_L + sdst0, pa_l);
        cp16(sb + ARR_A_L + sdst1, pa_l + 8);
        cp16(sb + ARR_W_H + sdst0, pw_h);
        cp16(sb + ARR_W_H + sdst1, pw_h + 8);
        cp16(sb + ARR_W_L + sdst0, pw_l);
        cp16(sb + ARR_W_L + sdst1, pw_l + 8);
    };

    float acc[4][4][4];
#pragma unroll
    for (int i = 0; i < 4; i++)
#pragma unroll
        for (int j = 0; j < 4; j++)
#pragma unroll
            for (int q = 0; q < 4; q++) acc[i][j][q] = 0.f;

    // prologue: stages 0 and 1
    load_stage(0, 0);
    asm volatile("cp.async.commit_group;");
    load_stage(1, 32);
    asm volatile("cp.async.commit_group;");

    const int arow = wm + (lane & 7) + (lane & 8);
    const int brow = wn + (lane & 7) + ((lane >> 4) << 3);

    for (int s = 0; s < nsteps; s++) {
        asm volatile("cp.async.wait_group 1;");   // stage s resident
        __syncthreads();                          // all warps past step s-1
        if (s + 2 < nsteps) load_stage((s + 2) % NSTAGE, (s + 2) * 32);
        asm volatile("cp.async.commit_group;");

        const unsigned sb = sbase + (s % NSTAGE) * STAGE_BYTES;
#pragma unroll
        for (int kk = 0; kk < 32; kk += 16) {
            const int acol = kk + ((lane >> 4) << 3);
            const int bcol = kk + (lane & 8);
            unsigned af[4][4];
            unsigned whf[4][2], wlf[4][2];
#pragma unroll
            for (int mi = 0; mi < 4; mi++)
                ldsm_x4(af[mi], sb + ARR_A_H + swz(arow + mi * 16, acol));
#pragma unroll
            for (int nj = 0; nj < 2; nj++) {
                unsigned r[4];
                ldsm_x4(r, sb + ARR_W_H + swz(brow + nj * 16, bcol));
                whf[nj * 2][0] = r[0]; whf[nj * 2][1] = r[1];
                whf[nj * 2 + 1][0] = r[2]; whf[nj * 2 + 1][1] = r[3];
                ldsm_x4(r, sb + ARR_W_L + swz(brow + nj * 16, bcol));
                wlf[nj * 2][0] = r[0]; wlf[nj * 2][1] = r[1];
                wlf[nj * 2 + 1][0] = r[2]; wlf[nj * 2 + 1][1] = r[3];
            }
#pragma unroll
            for (int mi = 0; mi < 4; mi++)
#pragma unroll
                for (int ni = 0; ni < 4; ni++) {
                    mma_bf16(acc[mi][ni], af[mi], whf[ni]);
                    mma_bf16(acc[mi][ni], af[mi], wlf[ni]);
                }
#pragma unroll
            for (int mi = 0; mi < 4; mi++)
                ldsm_x4(af[mi], sb + ARR_A_L + swz(arow + mi * 16, acol));
#pragma unroll
            for (int mi = 0; mi < 4; mi++)
#pragma unroll
                for (int ni = 0; ni < 4; ni++)
                    mma_bf16(acc[mi][ni], af[mi], whf[ni]);
        }
    }

    // epilogue
#pragma unroll
    for (int mi = 0; mi < 4; mi++) {
        int r0 = m0 + wm + mi * 16 + (lane >> 2);
#pragma unroll
        for (int ni = 0; ni < 4; ni++) {
            int c = n0 + wn + ni * 8 + (lane & 3) * 2;
            *(float2*)&C[(size_t)r0 * ldc + c] =
                make_float2(acc[mi][ni][0], acc[mi][ni][1]);
            *(float2*)&C[(size_t)(r0 + 8) * ldc + c] =
                make_float2(acc[mi][ni][2], acc[mi][ni][3]);
        }
    }
}

// ---------------------------------------------------------------------------
// x_proj SIMT GEMM: dbc[TT,80] = xc[TT,DIN] @ Wx[80,DIN]^T
// ---------------------------------------------------------------------------
__global__ void __launch_bounds__(256)
gemm_xproj_kernel(const float* __restrict__ A, const float* __restrict__ W,
                  float* __restrict__ C) {
    __shared__ float As[16][68];
    __shared__ float Ws[16][17];
    const int tid = threadIdx.x;
    const int tx = tid & 15, ty = tid >> 4;
    const int m0 = blockIdx.y * 64, n0 = blockIdx.x * 16;
    const int lrow = tid >> 2;
    const int lq = (tid & 3) * 4;

    float acc[4] = {0.f, 0.f, 0.f, 0.f};

    for (int k0 = 0; k0 < DIN; k0 += 16) {
        float4 av = *(const float4*)(A + (size_t)(m0 + lrow) * DIN + k0 + lq);
        As[lq + 0][lrow] = av.x; As[lq + 1][lrow] = av.y;
        As[lq + 2][lrow] = av.z; As[lq + 3][lrow] = av.w;
        if (tid < 64) {
            int wr = tid >> 2, wq = (tid & 3) * 4;
            float4 wv = *(const float4*)(W + (size_t)(n0 + wr) * DIN + k0 + wq);
            Ws[wq + 0][wr] = wv.x; Ws[wq + 1][wr] = wv.y;
            Ws[wq + 2][wr] = wv.z; Ws[wq + 3][wr] = wv.w;
        }
        __syncthreads();
#pragma unroll
        for (int kk = 0; kk < 16; kk++) {
            float4 a = *(const float4*)(&As[kk][ty * 4]);
            float wv = Ws[kk][tx];
            acc[0] += a.x * wv; acc[1] += a.y * wv;
            acc[2] += a.z * wv; acc[3] += a.w * wv;
        }
        __syncthreads();
    }
#pragma unroll
    for (int i = 0; i < 4; i++)
        C[(size_t)(m0 + ty * 4 + i) * NR + n0 + tx] = acc[i];
}

// ---------------------------------------------------------------------------
// dt GEMM (SIMT, K=48): dt = softplus(dbc[:,:48] @ Wdt^T + bdt)
// ---------------------------------------------------------------------------
__global__ void __launch_bounds__(256)
gemm_dt_kernel(const float* __restrict__ A, int lda,
               const float* __restrict__ W,
               const float* __restrict__ bias,
               float* __restrict__ C, int ldc, int N, int K) {
    __shared__ float As[16][132];
    __shared__ float Ws[16][68];
    const int tid = threadIdx.x;
    const int tx = tid & 15, ty = tid >> 4;
    const int m0 = blockIdx.y * 128, n0 = blockIdx.x * 64;
    const int ar = tid >> 1;
    const int ak = (tid & 1) * 8;
    const int wr = tid >> 2;
    const int wk = (tid & 3) * 4;

    float acc[8][4];
#pragma unroll
    for (int i = 0; i < 8; i++)
#pragma unroll
        for (int j = 0; j < 4; j++) acc[i][j] = 0.f;

    for (int k0 = 0; k0 < K; k0 += 16) {
        const float* ap = A + (size_t)(m0 + ar) * lda + k0 + ak;
        float4 a0 = *(const float4*)(ap);
        float4 a1 = *(const float4*)(ap + 4);
        As[ak + 0][ar] = a0.x; As[ak + 1][ar] = a0.y;
        As[ak + 2][ar] = a0.z; As[ak + 3][ar] = a0.w;
        As[ak + 4][ar] = a1.x; As[ak + 5][ar] = a1.y;
        As[ak + 6][ar] = a1.z; As[ak + 7][ar] = a1.w;
        float4 wv = *(const float4*)(W + (size_t)(n0 + wr) * K + k0 + wk);
        Ws[wk + 0][wr] = wv.x; Ws[wk + 1][wr] = wv.y;
        Ws[wk + 2][wr] = wv.z; Ws[wk + 3][wr] = wv.w;
        __syncthreads();
#pragma unroll
        for (int kk = 0; kk < 16; kk++) {
            float4 av0 = *(const float4*)(&As[kk][ty * 8]);
            float4 av1 = *(const float4*)(&As[kk][ty * 8 + 4]);
            float4 wv0 = *(const float4*)(&Ws[kk][tx * 4]);
            float a[8] = {av0.x, av0.y, av0.z, av0.w, av1.x, av1.y, av1.z, av1.w};
            float w[4] = {wv0.x, wv0.y, wv0.z, wv0.w};
#pragma unroll
            for (int i = 0; i < 8; i++)
#pragma unroll
                for (int j = 0; j < 4; j++)
                    acc[i][j] += a[i] * w[j];
        }
        __syncthreads();
    }
#pragma unroll
    for (int i = 0; i < 8; i++) {
        int m = m0 + ty * 8 + i;
#pragma unroll
        for (int j = 0; j < 4; j++) {
            int n = n0 + tx * 4 + j;
            float v = acc[i][j] + bias[n];
            v = (v > 20.f) ? v : log1pf(__expf(v));
            C[(size_t)m * ldc + n] = v;
        }
    }
}

// ---------------------------------------------------------------------------
// Causal depthwise conv (KC=4, left pad 3) + bias + SiLU.
// ---------------------------------------------------------------------------
__global__ void __launch_bounds__(256)
conv_kernel(const float* __restrict__ xz, float* __restrict__ xc,
            const float* __restrict__ cw, const float* __restrict__ cb) {
    int idx = blockIdx.x * blockDim.x + threadIdx.x;
    if (idx >= TT * DIN) return;
    int c = idx % DIN;
    int tb = idx / DIN;
    int t = tb % LL;
    int b = tb / LL;
    float acc = cb[c];
#pragma unroll
    for (int k = 0; k < KCC; k++) {
        int tt = t - (KCC - 1) + k;
        if (tt >= 0)
            acc += cw[c * KCC + k] * xz[((size_t)(b * LL + tt)) * (2 * DIN) + c];
    }
    float sg = 1.f / (1.f + __expf(-acc));
    xc[idx] = acc * sg;
}

// ===========================================================================
// Chunked selective scan (3 phases).
// Thread = one (b, d, n) state. Block: 16 d x 16 n. grid.x = BB*96, grid.y = CH.
// ===========================================================================
// Phase 1: local scan from h=0; emit chunk-end h and decay product
// P = exp(Av * sum(dt)) (analytic collapse of prod exp(dt*Av)).
__global__ void __launch_bounds__(256)
scan_p1_kernel(const float* __restrict__ dt, const float* __restrict__ xc,
               const float* __restrict__ dbc, const float* __restrict__ Alog) {
    int warp = threadIdx.x >> 5;
    int lane = threadIdx.x & 31;
    int n = lane & 15;
    int dl = lane >> 4;
    constexpr int BLOCKS_PER_B = DIN / 16;   // 96
    int b = blockIdx.x / BLOCKS_PER_B;
    int d = (blockIdx.x % BLOCKS_PER_B) * 16 + warp * 2 + dl;
    int c = blockIdx.y;

    float Av = -__expf(Alog[d * NSS + n]);
    float h = 0.f, sdt = 0.f;
    size_t rowbase = (size_t)b * LL + (size_t)c * CS;

    for (int t = 0; t < CS; t++) {
        size_t row = rowbase + t;
        float dtv = dt[row * DIN + d];
        float xv  = xc[row * DIN + d];
        float Bv  = dbc[row * NR + DRR + n];
        sdt += dtv;
        h = __expf(dtv * Av) * h + (dtv * xv) * Bv;
    }
    int idx = (b * DIN + d) * NSS + n;
    g_hend[(size_t)c * NSTATE + idx] = h;
    g_P[(size_t)c * NSTATE + idx]   = __expf(Av * sdt);
}

// Phase 2: sequential chain over chunks (elementwise, 8 steps).
__global__ void __launch_bounds__(256)
scan_chain_kernel() {
    int i = blockIdx.x * 256 + threadIdx.x;
    if (i >= NSTATE) return;
    float hin = 0.f;
#pragma unroll
    for (int c = 0; c < CH; c++) {
        g_hinit[(size_t)c * NSTATE + i] = hin;
        hin = g_P[(size_t)c * NSTATE + i] * hin + g_hend[(size_t)c * NSTATE + i];
    }
}

// Phase 3: re-run chunk from correct initial state; emit gated y (bf16 hi/lo).
__global__ void __launch_bounds__(256)
scan_p2_kernel(const float* __restrict__ dt, const float* __restrict__ xc,
               const float* __restrict__ dbc, const float* __restrict__ xz,
               __nv_bfloat16* __restrict__ yh, __nv_bfloat16* __restrict__ yl,
               const float* __restrict__ Alog, const float* __restrict__ Dp) {
    int warp = threadIdx.x >> 5;
    int lane = threadIdx.x & 31;
    int n = lane & 15;
    int dl = lane >> 4;
    constexpr int BLOCKS_PER_B = DIN / 16;
    int b = blockIdx.x / BLOCKS_PER_B;
    int d = (blockIdx.x % BLOCKS_PER_B) * 16 + warp * 2 + dl;
    int c = blockIdx.y;

    float Av = -__expf(Alog[d * NSS + n]);
    float Dv = Dp[d];
    int idx = (b * DIN + d) * NSS + n;
    float h = g_hinit[(size_t)c * NSTATE + idx];
    size_t rowbase = (size_t)b * LL + (size_t)c * CS;

    for (int t = 0; t < CS; t++) {
        size_t row = rowbase + t;
        float dtv = dt[row * DIN + d];
        float xv  = xc[row * DIN + d];
        float Bv  = dbc[row * NR + DRR + n];
        float Cv  = dbc[row * NR + DRR + NSS + n];
        h = __expf(dtv * Av) * h + (dtv * xv) * Bv;
        float yp = h * Cv;
        yp += __shfl_xor_sync(0xffffffffu, yp, 8);
        yp += __shfl_xor_sync(0xffffffffu, yp, 4);
        yp += __shfl_xor_sync(0xffffffffu, yp, 2);
        yp += __shfl_xor_sync(0xffffffffu, yp, 1);
        if (n == 0) {
            float zv = xz[row * (2 * DIN) + DIN + d];
            float sg = zv / (1.f + __expf(-zv));
            float g = (yp + xv * Dv) * sg;
            __nv_bfloat16 gh = __float2bfloat16(g);
            yh[row * DIN + d] = gh;
            yl[row * DIN + d] = __float2bfloat16(g - __bfloat162float(gh));
        }
    }
}

// ---------------------------------------------------------------------------
// Orchestration
// ---------------------------------------------------------------------------
extern "C" void kernel_launch(void* const* d_in, const int* in_sizes, int n_in,
                              void* d_out, int out_size) {
    const float* x        = (const float*)d_in[0];
    const float* ln_w     = (const float*)d_in[1];
    const float* ln_b     = (const float*)d_in[2];
    const float* in_proj  = (const float*)d_in[3];
    const float* conv_w   = (const float*)d_in[4];
    const float* conv_b   = (const float*)d_in[5];
    const float* x_proj   = (const float*)d_in[6];
    const float* dt_w     = (const float*)d_in[7];
    const float* dt_b     = (const float*)d_in[8];
    const float* A_log    = (const float*)d_in[9];
    const float* D_skip   = (const float*)d_in[10];
    const float* out_proj = (const float*)d_in[11];
    const float* fn_w     = (const float*)d_in[12];
    const float* fn_b     = (const float*)d_in[13];
    float* out = (float*)d_out;

    float* base = nullptr;
    cudaGetSymbolAddress((void**)&base, g_buf);
    float* bx   = base + O_X;
    float* bres = base + O_RES;
    float* bxz  = base + O_XZ;
    float* bxc  = base + O_XC;
    float* bdbc = base + O_DBC;
    float* bdt  = base + O_DT;

    __nv_bfloat16 *xnh, *xnl, *yh, *yl, *wih, *wil, *woh, *wol;
    cudaGetSymbolAddress((void**)&xnh, g_xn_h);
    cudaGetSymbolAddress((void**)&xnl, g_xn_l);
    cudaGetSymbolAddress((void**)&yh,  g_y_h);
    cudaGetSymbolAddress((void**)&yl,  g_y_l);
    cudaGetSymbolAddress((void**)&wih, g_wi_h);
    cudaGetSymbolAddress((void**)&wil, g_wi_l);
    cudaGetSymbolAddress((void**)&woh, g_wo_h);
    cudaGetSymbolAddress((void**)&wol, g_wo_l);

    cudaFuncSetAttribute(gemm_tc2_kernel,
                         cudaFuncAttributeMaxDynamicSharedMemorySize,
                         NSTAGE * STAGE_BYTES);

    cvt_weights_kernel<<<(unsigned)((NWI + NWO + 255) / 256), 256>>>(in_proj, out_proj);
    init_kernel<<<(TT * DD) / 256, 256>>>(x, bx, bres);

    for (int l = 0; l < NLAY; l++) {
        layer_ln_kernel<<<TT, 256>>>(bx, bres, xnh, xnl,
                                     ln_w + (size_t)l * DD, ln_b + (size_t)l * DD);
        // xz = xn @ Wi^T   (2048 x 3072, K=768)
        gemm_tc2_kernel<<<dim3((2 * DIN) / 128, TT / 128), 256,
                          NSTAGE * STAGE_BYTES>>>(
            xnh, xnl,
            wih + (size_t)l * 2 * DIN * DD, wil + (size_t)l * 2 * DIN * DD,
            bxz, 2 * DIN, DD);
        // xc = silu(conv(xi) + cb)
        conv_kernel<<<(TT * DIN) / 256, 256>>>(
            bxz, bxc, conv_w + (size_t)l * DIN * KCC, conv_b + (size_t)l * DIN);
        // dbc = xc @ Wx^T  (2048 x 80, K=1536)
        gemm_xproj_kernel<<<dim3(NR / 16, TT / 64), 256>>>(
            bxc, x_proj + (size_t)l * NR * DIN, bdbc);
        // dt = softplus(dbc[:, :48] @ Wdt^T + bdt)
        gemm_dt_kernel<<<dim3(DIN / 64, TT / 128), 256>>>(
            bdbc, NR, dt_w + (size_t)l * DIN * DRR, dt_b + (size_t)l * DIN,
            bdt, DIN, DIN, DRR);
        // chunked selective scan
        scan_p1_kernel<<<dim3(BB * (DIN / 16), CH), 256>>>(
            bdt, bxc, bdbc, A_log + (size_t)l * DIN * NSS);
        scan_chain_kernel<<<(NSTATE + 255) / 256, 256>>>();
        scan_p2_kernel<<<dim3(BB * (DIN / 16), CH), 256>>>(
            bdt, bxc, bdbc, bxz, yh, yl,
            A_log + (size_t)l * DIN * NSS, D_skip + (size_t)l * DIN);
        // x_next = y @ Wo^T  (2048 x 768, K=1536)
        gemm_tc2_kernel<<<dim3(DD / 128, TT / 128), 256,
                          NSTAGE * STAGE_BYTES>>>(
            yh, yl,
            woh + (size_t)l * DD * DIN, wol + (size_t)l * DD * DIN,
            bx, DD, DIN);
    }

    final_ln_kernel<<<TT, 256>>>(bx, bres, fn_w, fn_b, out);
}